// round 3
// baseline (speedup 1.0000x reference)
#include <cuda_runtime.h>

#define NB   16384
#define NJ   12
#define NQ   7
#define NO   5
#define NH1  128
#define NH2  128
#define GS   4
#define NBLOCKS (NB / GS)

#define W1_SZ (NQ * (NO + 1) * NH1)     // 5376
#define W2_SZ ((NH1 + 1) * NH2)         // 16512
#define V_SZ  (NQ * (NH2 + 1) * NO)     // 4515

// ---------------- device scratch (no allocation allowed) ----------------
__device__ int   g_mode64;              // 1 if judge_ids buffer is int64
__device__ int   g_count[NJ];
__device__ int   g_cursor[NJ];
__device__ int   g_perm[NB];
__device__ float g_cW1[NJ * W1_SZ];     // [j][q][i=0..5][h]
__device__ float g_cW2[NJ * W2_SZ];     // [j][i=0..128][h]
__device__ float g_cV [NJ * V_SZ];      // [j][q][i=0..128][o]

// ---------------- helpers ----------------
__device__ __forceinline__ float sigmoidf(float v) {
    return 1.0f / (1.0f + __expf(-v));
}

__device__ __forceinline__ unsigned long long pk(float a, float b) {
    unsigned long long r;
    asm("mov.b64 %0, {%1, %2};" : "=l"(r) : "f"(a), "f"(b));
    return r;
}
__device__ __forceinline__ void upk(unsigned long long v, float& lo, float& hi) {
    asm("mov.b64 {%0, %1}, %2;" : "=f"(lo), "=f"(hi) : "l"(v));
}
__device__ __forceinline__ void ffma2(unsigned long long& d,
                                      unsigned long long a,
                                      unsigned long long b) {
    asm("fma.rn.f32x2 %0, %1, %2, %0;" : "+l"(d) : "l"(a), "l"(b));
}

// ---------------- dtype detection + bin zeroing ----------------
// Reads only the first NB 32-bit words (safe for both int32[NB] and int64[NB]).
// If all odd words are zero -> int64 little-endian (values 0..11), else int32.
__global__ void k_detect(const int* __restrict__ jw) {
    __shared__ int s_any;
    if (threadIdx.x == 0) s_any = 0;
    __syncthreads();
    int v = 0;
    for (int i = 1 + 2 * (int)threadIdx.x; i < NB; i += 2 * (int)blockDim.x)
        v |= jw[i];
    if (v) atomicOr(&s_any, 1);
    __syncthreads();
    if (threadIdx.x == 0) g_mode64 = (s_any == 0) ? 1 : 0;
    if (threadIdx.x < NJ) g_count[threadIdx.x] = 0;
}

__global__ void k_count(const int* __restrict__ jw) {
    int m = g_mode64;
    for (int b = blockIdx.x * blockDim.x + threadIdx.x; b < NB;
         b += gridDim.x * blockDim.x) {
        int j = m ? jw[2 * b] : jw[b];
        atomicAdd(&g_count[j], 1);
    }
}

__global__ void k_scan() {
    if (threadIdx.x == 0) {
        int acc = 0;
        for (int j = 0; j < NJ; j++) { g_cursor[j] = acc; acc += g_count[j]; }
    }
}

__global__ void k_scatter(const int* __restrict__ jw) {
    int m = g_mode64;
    for (int b = blockIdx.x * blockDim.x + threadIdx.x; b < NB;
         b += gridDim.x * blockDim.x) {
        int j = m ? jw[2 * b] : jw[b];
        int p = atomicAdd(&g_cursor[j], 1);
        g_perm[p] = b;
    }
}

// ---------------- combined weights: W + W_a[j] ----------------
__global__ void k_weights(const float* __restrict__ W1, const float* __restrict__ W1a,
                          const float* __restrict__ W2, const float* __restrict__ W2a,
                          const float* __restrict__ V,  const float* __restrict__ Va) {
    const int n1 = NJ * W1_SZ;
    const int n2 = NJ * W2_SZ;
    const int n3 = NJ * V_SZ;
    const int total = n1 + n2 + n3;
    for (int i = blockIdx.x * blockDim.x + threadIdx.x; i < total;
         i += gridDim.x * blockDim.x) {
        if (i < n1) {
            g_cW1[i] = W1[i % W1_SZ] + W1a[i];
        } else if (i < n1 + n2) {
            int r = i - n1;
            g_cW2[r] = W2[r % W2_SZ] + W2a[r];
        } else {
            int r = i - n1 - n2;
            g_cV[r] = V[r % V_SZ] + Va[r];
        }
    }
}

// ---------------- fused MLP, GS same-judge samples per block ----------------
__global__ void __launch_bounds__(128)
k_main(const float* __restrict__ x, const int* __restrict__ jw,
       float* __restrict__ out) {
    __shared__ int   sb[GS], sj[GS];
    __shared__ float xs[GS][NQ][NO];                        // 140 f
    __shared__ __align__(16) float z1v[NH1][NQ][GS];        // [i-1][q][s]
    __shared__ float z2s[GS][NQ][NH2 + 1];
    __shared__ float lg[GS * NQ][NO];

    const int tid = threadIdx.x;

    if (tid < GS) {
        int b = g_perm[blockIdx.x * GS + tid];
        sb[tid] = b;
        sj[tid] = g_mode64 ? jw[2 * b] : jw[b];
    }
    __syncthreads();

    for (int t = tid; t < GS * NQ * NO; t += 128) {
        int s = t / (NQ * NO), r = t % (NQ * NO);
        (&xs[0][0][0])[t] = x[sb[s] * (NQ * NO) + r];
    }
    const int j0 = sj[0], j1 = sj[1], j2 = sj[2], j3 = sj[3];
    const bool uni = (j0 == j1) & (j1 == j2) & (j2 == j3);
    __syncthreads();

    // ---------- layer 1 ----------
    const float* b1[GS] = { g_cW1 + j0 * W1_SZ, g_cW1 + j1 * W1_SZ,
                            g_cW1 + j2 * W1_SZ, g_cW1 + j3 * W1_SZ };
    float a1[GS][NQ];
    #pragma unroll
    for (int q = 0; q < NQ; q++) {
        #pragma unroll
        for (int i = 0; i <= NO; i++) {
            int off = (q * (NO + 1) + i) * NH1 + tid;
            float w[GS];
            w[0] = b1[0][off];
            if (uni) { w[1] = w[0]; w[2] = w[0]; w[3] = w[0]; }
            else     { w[1] = b1[1][off]; w[2] = b1[2][off]; w[3] = b1[3][off]; }
            #pragma unroll
            for (int s = 0; s < GS; s++)
                a1[s][q] = (i == 0) ? w[s] : fmaf(xs[s][q][i - 1], w[s], a1[s][q]);
        }
    }
    #pragma unroll
    for (int q = 0; q < NQ; q++)
        #pragma unroll
        for (int s = 0; s < GS; s++)
            z1v[tid][q][s] = sigmoidf(a1[s][q]);
    __syncthreads();

    // ---------- layer 2 (f32x2 packed accumulators) ----------
    const float* b2[GS] = { g_cW2 + j0 * W2_SZ, g_cW2 + j1 * W2_SZ,
                            g_cW2 + j2 * W2_SZ, g_cW2 + j3 * W2_SZ };
    unsigned long long a01[NQ], a23[NQ];
    {
        float w[GS];
        w[0] = b2[0][tid];  // bias row i=0
        if (uni) { w[1] = w[0]; w[2] = w[0]; w[3] = w[0]; }
        else     { w[1] = b2[1][tid]; w[2] = b2[2][tid]; w[3] = b2[3][tid]; }
        unsigned long long p01 = pk(w[0], w[1]);
        unsigned long long p23 = pk(w[2], w[3]);
        #pragma unroll
        for (int q = 0; q < NQ; q++) { a01[q] = p01; a23[q] = p23; }
    }
    #pragma unroll 2
    for (int i = 1; i <= NH1; i++) {
        int off = i * NH2 + tid;
        float w0 = b2[0][off];
        unsigned long long p01, p23;
        if (uni) {
            p01 = pk(w0, w0);
            p23 = p01;
        } else {
            float w1v = b2[1][off], w2v = b2[2][off], w3v = b2[3][off];
            p01 = pk(w0, w1v);
            p23 = pk(w2v, w3v);
        }
        const ulonglong2* zr = (const ulonglong2*)&z1v[i - 1][0][0];
        #pragma unroll
        for (int q = 0; q < NQ; q++) {
            ulonglong2 z = zr[q];      // {z[s0],z[s1]}, {z[s2],z[s3]}
            ffma2(a01[q], z.x, p01);
            ffma2(a23[q], z.y, p23);
        }
    }
    #pragma unroll
    for (int q = 0; q < NQ; q++) {
        float v0, v1, v2, v3;
        upk(a01[q], v0, v1);
        upk(a23[q], v2, v3);
        z2s[0][q][1 + tid] = sigmoidf(v0);
        z2s[1][q][1 + tid] = sigmoidf(v1);
        z2s[2][q][1 + tid] = sigmoidf(v2);
        z2s[3][q][1 + tid] = sigmoidf(v3);
    }
    if (tid < GS * NQ) z2s[tid / NQ][tid % NQ][0] = 1.0f;
    __syncthreads();

    // ---------- layer 3: logits ----------
    for (int t = tid; t < GS * NQ * NO; t += 128) {
        int s = t / (NQ * NO), r = t % (NQ * NO), q = r / NO, o = r % NO;
        const float* vb = g_cV + (sj[s] * NQ + q) * ((NH2 + 1) * NO) + o;
        const float* zz = &z2s[s][q][0];
        float acc0 = 0.f, acc1 = 0.f;
        #pragma unroll 8
        for (int i = 0; i < NH2; i += 2) {
            acc0 = fmaf(zz[i],     vb[i * NO],        acc0);
            acc1 = fmaf(zz[i + 1], vb[(i + 1) * NO],  acc1);
        }
        acc0 = fmaf(zz[NH2], vb[NH2 * NO], acc0);
        lg[s * NQ + q][o] = acc0 + acc1;
    }
    __syncthreads();

    // ---------- softmax + store ----------
    if (tid < GS * NQ) {
        int s = tid / NQ, q = tid % NQ;
        float m = lg[tid][0];
        #pragma unroll
        for (int o = 1; o < NO; o++) m = fmaxf(m, lg[tid][o]);
        float e[NO], sum = 0.f;
        #pragma unroll
        for (int o = 0; o < NO; o++) { e[o] = __expf(lg[tid][o] - m); sum += e[o]; }
        float inv = 1.0f / sum;
        float* op = out + (sb[s] * NQ + q) * NO;
        #pragma unroll
        for (int o = 0; o < NO; o++) op[o] = e[o] * inv;
    }
}

// ---------------- launch ----------------
extern "C" void kernel_launch(void* const* d_in, const int* in_sizes, int n_in,
                              void* d_out, int out_size) {
    const float* x   = (const float*)d_in[0];
    const int*   jw  = (const int*)  d_in[1];
    const float* W1  = (const float*)d_in[2];
    const float* W1a = (const float*)d_in[3];
    const float* W2  = (const float*)d_in[4];
    const float* W2a = (const float*)d_in[5];
    const float* V   = (const float*)d_in[6];
    const float* Va  = (const float*)d_in[7];
    float* out = (float*)d_out;

    k_detect <<<1, 256>>>(jw);
    k_count  <<<64, 256>>>(jw);
    k_scan   <<<1, 32>>>();
    k_scatter<<<64, 256>>>(jw);
    k_weights<<<620, 512>>>(W1, W1a, W2, W2a, V, Va);
    k_main   <<<NBLOCKS, 128>>>(x, jw, out);
}

// round 4
// speedup vs baseline: 1.1350x; 1.1350x over previous
#include <cuda_runtime.h>

#define NB   16384
#define NJ   12
#define NQ   7
#define NO   5
#define NH1  128
#define NH2  128
#define GS   4
#define NBLOCKS (NB / GS)

#define W1_SZ (NQ * (NO + 1) * NH1)     // 5376
#define W2_SZ ((NH1 + 1) * NH2)         // 16512
#define VT_ROW 132                      // 129 + 3 pad (16B-aligned rows)
#define VT_SZ (NQ * NO * VT_ROW)        // 4620

#define PREP_BLOCKS 64
#define PREP_THREADS 256

// ---------------- device scratch (no allocation allowed) ----------------
__device__ int   g_mode64;
__device__ int   g_count[NJ];
__device__ int   g_cursor[NJ];
__device__ int   g_ticket;
__device__ int   g_go;
__device__ int   g_perm[NB];
__device__ float g_cW1[NJ * W1_SZ];          // [j][q][i=0..5][h]
__device__ float g_cW2[NJ * W2_SZ];          // [j][i=0..128][h]
__device__ float g_cVt[NJ * VT_SZ];          // [j][q][o][i=0..131] transposed+padded

// ---------------- helpers ----------------
__device__ __forceinline__ float sigmoidf(float v) {
    return 1.0f / (1.0f + __expf(-v));
}
__device__ __forceinline__ unsigned long long pk(float a, float b) {
    unsigned long long r;
    asm("mov.b64 %0, {%1, %2};" : "=l"(r) : "f"(a), "f"(b));
    return r;
}
__device__ __forceinline__ void upk(unsigned long long v, float& lo, float& hi) {
    asm("mov.b64 {%0, %1}, %2;" : "=f"(lo), "=f"(hi) : "l"(v));
}
__device__ __forceinline__ void ffma2(unsigned long long& d,
                                      unsigned long long a,
                                      unsigned long long b) {
    asm("fma.rn.f32x2 %0, %1, %2, %0;" : "+l"(d) : "l"(a), "l"(b));
}

// ================= ONE prologue kernel =================
// count (atomics) -> ticket -> last block scans+resets -> all blocks do the
// weight-combine while waiting -> spin on flag -> scatter.
// All 64 blocks are co-resident (64 << 148 SMs), so the spin cannot deadlock.
__global__ void __launch_bounds__(PREP_THREADS)
k_prep(const int* __restrict__ jw,
       const float* __restrict__ W1, const float* __restrict__ W1a,
       const float* __restrict__ W2, const float* __restrict__ W2a,
       const float* __restrict__ V,  const float* __restrict__ Va) {
    __shared__ int s_any;
    __shared__ int s_cnt[NJ];
    const int tid = threadIdx.x;
    const int b = blockIdx.x * PREP_THREADS + tid;   // exactly one sample/thread

    if (tid == 0) s_any = 0;
    if (tid < NJ) s_cnt[tid] = 0;
    __syncthreads();

    // dtype detect: every block inspects odd 32-bit words jw[1..511].
    // int64 little-endian judge ids (0..11) -> all zero; int32 -> ~surely not.
    if (jw[2 * tid + 1] != 0) s_any = 1;   // benign race
    __syncthreads();
    const int m64 = (s_any == 0);

    const int j = m64 ? jw[2 * b] : jw[b];
    atomicAdd(&s_cnt[j], 1);
    __syncthreads();
    if (tid < NJ) {
        if (s_cnt[tid]) atomicAdd(&g_count[tid], s_cnt[tid]);
        __threadfence();
    }
    __syncthreads();

    if (tid == 0) {
        int t = atomicAdd(&g_ticket, 1);
        if (t == PREP_BLOCKS - 1) {            // last block: scan + reset
            int acc = 0;
            #pragma unroll
            for (int k = 0; k < NJ; k++) {
                int c = atomicAdd(&g_count[k], 0);   // strong read (L2)
                g_cursor[k] = acc; acc += c;
                g_count[k] = 0;                       // ready for next replay
            }
            g_mode64 = m64;
            g_ticket = 0;                             // ready for next replay
            __threadfence();
            atomicExch(&g_go, 1);
        }
    }

    // ---- independent work while waiting: combined weights + transposed V ----
    const int n1 = NJ * W1_SZ;
    const int n2 = NJ * W2_SZ;
    const int n3 = NJ * VT_SZ;
    const int total = n1 + n2 + n3;
    for (int i = blockIdx.x * PREP_THREADS + tid; i < total;
         i += PREP_BLOCKS * PREP_THREADS) {
        if (i < n1) {
            g_cW1[i] = W1[i % W1_SZ] + W1a[i];
        } else if (i < n1 + n2) {
            int r = i - n1;
            g_cW2[r] = W2[r % W2_SZ] + W2a[r];
        } else {
            int r = i - n1 - n2;
            int ii = r % VT_ROW;
            int rr = r / VT_ROW;          // ((j*NQ+q)*NO+o)
            int o  = rr % NO;
            int qq = (rr / NO) % NQ;
            int jj = rr / (NO * NQ);
            float v = 0.0f;               // zero the 3 pad lanes
            if (ii <= NH2)
                v = V[(qq * (NH2 + 1) + ii) * NO + o] +
                    Va[((jj * NQ + qq) * (NH2 + 1) + ii) * NO + o];
            g_cVt[r] = v;
        }
    }

    // ---- spin until cursors ready, then scatter ----
    if (tid == 0) {
        while (atomicAdd(&g_go, 0) == 0) __nanosleep(64);
    }
    __syncthreads();
    __threadfence();
    int pos = atomicAdd(&g_cursor[j], 1);
    g_perm[pos] = b;
}

// ================= fused MLP, GS same-judge samples per block =================
__global__ void __launch_bounds__(128)
k_main(const float* __restrict__ x, const int* __restrict__ jw,
       float* __restrict__ out) {
    __shared__ int   sb[GS], sj[GS];
    __shared__ float xs[GS][NQ][NO];
    // union region: layer1 output z1 [i=0..127][q][s] (3584 f)
    //               then layer2 output z2 [s][q][0..131]  (3696 f)
    __shared__ __align__(16) float zbuf[GS * NQ * VT_ROW];
    __shared__ __align__(16) float sVt[VT_SZ];          // this judge's V^T
    __shared__ float lg[GS * NQ][NO];

    const int tid = threadIdx.x;

    if (blockIdx.x == 0 && tid == 0) g_go = 0;          // reset for next replay

    if (tid < GS) {
        int b = g_perm[blockIdx.x * GS + tid];
        sb[tid] = b;
        sj[tid] = g_mode64 ? jw[2 * b] : jw[b];
    }
    __syncthreads();

    const int j0 = sj[0], j1 = sj[1], j2 = sj[2], j3 = sj[3];
    const bool uni = (j0 == j1) & (j1 == j2) & (j2 == j3);

    for (int t = tid; t < GS * NQ * NO; t += 128) {
        int s = t / (NQ * NO), r = t % (NQ * NO);
        (&xs[0][0][0])[t] = x[sb[s] * (NQ * NO) + r];
    }
    if (uni) {   // cache V^T slice for this judge (18 KB)
        const float4* src = (const float4*)(g_cVt + j0 * VT_SZ);
        float4* dst = (float4*)sVt;
        for (int t = tid; t < VT_SZ / 4; t += 128) dst[t] = src[t];
    }
    __syncthreads();

    // ---------- layer 1 ----------
    const float* b1[GS] = { g_cW1 + j0 * W1_SZ, g_cW1 + j1 * W1_SZ,
                            g_cW1 + j2 * W1_SZ, g_cW1 + j3 * W1_SZ };
    float a1[GS][NQ];
    #pragma unroll
    for (int q = 0; q < NQ; q++) {
        #pragma unroll
        for (int i = 0; i <= NO; i++) {
            int off = (q * (NO + 1) + i) * NH1 + tid;
            float w[GS];
            w[0] = b1[0][off];
            if (uni) { w[1] = w[0]; w[2] = w[0]; w[3] = w[0]; }
            else     { w[1] = b1[1][off]; w[2] = b1[2][off]; w[3] = b1[3][off]; }
            #pragma unroll
            for (int s = 0; s < GS; s++)
                a1[s][q] = (i == 0) ? w[s] : fmaf(xs[s][q][i - 1], w[s], a1[s][q]);
        }
    }
    #pragma unroll
    for (int q = 0; q < NQ; q++)
        #pragma unroll
        for (int s = 0; s < GS; s++)
            zbuf[tid * (NQ * GS) + q * GS + s] = sigmoidf(a1[s][q]);
    __syncthreads();

    // ---------- layer 2 (f32x2 packed accumulators) ----------
    const float* b2[GS] = { g_cW2 + j0 * W2_SZ, g_cW2 + j1 * W2_SZ,
                            g_cW2 + j2 * W2_SZ, g_cW2 + j3 * W2_SZ };
    unsigned long long a01[NQ], a23[NQ];
    {
        float w[GS];
        w[0] = b2[0][tid];  // bias row i=0
        if (uni) { w[1] = w[0]; w[2] = w[0]; w[3] = w[0]; }
        else     { w[1] = b2[1][tid]; w[2] = b2[2][tid]; w[3] = b2[3][tid]; }
        unsigned long long p01 = pk(w[0], w[1]);
        unsigned long long p23 = pk(w[2], w[3]);
        #pragma unroll
        for (int q = 0; q < NQ; q++) { a01[q] = p01; a23[q] = p23; }
    }
    #pragma unroll 4
    for (int i = 1; i <= NH1; i++) {
        int off = i * NH2 + tid;
        float w0 = b2[0][off];
        unsigned long long p01, p23;
        if (uni) {
            p01 = pk(w0, w0);
            p23 = p01;
        } else {
            float w1v = b2[1][off], w2v = b2[2][off], w3v = b2[3][off];
            p01 = pk(w0, w1v);
            p23 = pk(w2v, w3v);
        }
        const ulonglong2* zr = (const ulonglong2*)(zbuf + (i - 1) * (NQ * GS));
        #pragma unroll
        for (int q = 0; q < NQ; q++) {
            ulonglong2 z = zr[q];      // {z[s0],z[s1]}, {z[s2],z[s3]}
            ffma2(a01[q], z.x, p01);
            ffma2(a23[q], z.y, p23);
        }
    }
    __syncthreads();   // everyone done reading z1 before z2 overwrites zbuf

    #pragma unroll
    for (int q = 0; q < NQ; q++) {
        float v0, v1, v2, v3;
        upk(a01[q], v0, v1);
        upk(a23[q], v2, v3);
        zbuf[(0 * NQ + q) * VT_ROW + 1 + tid] = sigmoidf(v0);
        zbuf[(1 * NQ + q) * VT_ROW + 1 + tid] = sigmoidf(v1);
        zbuf[(2 * NQ + q) * VT_ROW + 1 + tid] = sigmoidf(v2);
        zbuf[(3 * NQ + q) * VT_ROW + 1 + tid] = sigmoidf(v3);
    }
    if (tid < GS * NQ) {                 // bias + zero pads
        float* row = &zbuf[tid * VT_ROW];
        row[0] = 1.0f; row[129] = 0.0f; row[130] = 0.0f; row[131] = 0.0f;
    }
    __syncthreads();

    // ---------- layer 3: logits via smem-cached transposed V ----------
    for (int t = tid; t < GS * NQ * NO; t += 128) {
        int s = t / (NQ * NO), r = t % (NQ * NO), q = r / NO, o = r % NO;
        const ulonglong2* vz = (const ulonglong2*)(zbuf + (s * NQ + q) * VT_ROW);
        const ulonglong2* vv = uni
            ? (const ulonglong2*)(sVt + (q * NO + o) * VT_ROW)
            : (const ulonglong2*)(g_cVt + (sj[s] * NQ * NO + q * NO + o) * VT_ROW);
        unsigned long long acc0 = 0ULL, acc1 = 0ULL;   // = pk(0,0)
        #pragma unroll
        for (int k = 0; k < VT_ROW / 4; k++) {
            ulonglong2 a = vz[k], bb = vv[k];
            ffma2(acc0, a.x, bb.x);
            ffma2(acc1, a.y, bb.y);
        }
        float f0, f1, f2, f3;
        upk(acc0, f0, f1);
        upk(acc1, f2, f3);
        lg[s * NQ + q][o] = (f0 + f1) + (f2 + f3);
    }
    __syncthreads();

    // ---------- softmax + store ----------
    if (tid < GS * NQ) {
        int s = tid / NQ, q = tid % NQ;
        float m = lg[tid][0];
        #pragma unroll
        for (int o = 1; o < NO; o++) m = fmaxf(m, lg[tid][o]);
        float e[NO], sum = 0.f;
        #pragma unroll
        for (int o = 0; o < NO; o++) { e[o] = __expf(lg[tid][o] - m); sum += e[o]; }
        float inv = 1.0f / sum;
        float* op = out + (sb[s] * NQ + q) * NO;
        #pragma unroll
        for (int o = 0; o < NO; o++) op[o] = e[o] * inv;
    }
}

// ---------------- launch ----------------
extern "C" void kernel_launch(void* const* d_in, const int* in_sizes, int n_in,
                              void* d_out, int out_size) {
    const float* x   = (const float*)d_in[0];
    const int*   jw  = (const int*)  d_in[1];
    const float* W1  = (const float*)d_in[2];
    const float* W1a = (const float*)d_in[3];
    const float* W2  = (const float*)d_in[4];
    const float* W2a = (const float*)d_in[5];
    const float* V   = (const float*)d_in[6];
    const float* Va  = (const float*)d_in[7];
    float* out = (float*)d_out;

    k_prep<<<PREP_BLOCKS, PREP_THREADS>>>(jw, W1, W1a, W2, W2a, V, Va);
    k_main<<<NBLOCKS, 128>>>(x, jw, out);
}